// round 4
// baseline (speedup 1.0000x reference)
#include <cuda_runtime.h>

// QuantumRecurrentUnit — closed-form reduction.
//
// Per step, per batch element:
//   theta_q = prev_q + x[b][t][q]          (q = 0..5)
//   P_m     = prod_{q<=m} cos(theta_q)
//   out_m   = cos(w_m)*P_m - sin(w_m)*sin(theta_m)*sin(theta_{m+1})   (m < 5)
//   out_5   = cos(w_5)*P_5 - sin(w_5)*sin(theta_5)
//   prev    = out
//
// Derivation: pre-CNOT state is a product state (RY(a)RY(b)|0> = RY(a+b)|0>);
// the CNOT ladder is the prefix-XOR basis permutation P, and in the Heisenberg
// picture P^T Z_m P = Z_0...Z_m, P^T X_m P = X_m X_{m+1}; RY(w)^T Z RY(w) =
// cos(w) Z - sin(w) X. Product-state expectations give the formula above.

#define NQ 6
#define T_STEPS 1024
#define C_IN 16

__global__ void __launch_bounds__(32, 1)
qru_kernel(const float* __restrict__ x, const float* __restrict__ w,
           float* __restrict__ out, int B) {
    int b = blockIdx.x * 32 + threadIdx.x;
    if (b >= B) return;

    // Per-wire weight sincos (runtime input, computed once).
    float cw0, sw0, cw1, sw1, cw2, sw2, cw3, sw3, cw4, sw4, cw5, sw5;
    __sincosf(__ldg(w + 0), &sw0, &cw0);
    __sincosf(__ldg(w + 1), &sw1, &cw1);
    __sincosf(__ldg(w + 2), &sw2, &cw2);
    __sincosf(__ldg(w + 3), &sw3, &cw3);
    __sincosf(__ldg(w + 4), &sw4, &cw4);
    __sincosf(__ldg(w + 5), &sw5, &cw5);

    const float4* __restrict__ xp =
        reinterpret_cast<const float4*>(x + (size_t)b * (T_STEPS * C_IN));
    float* __restrict__ op = out + (size_t)b * (T_STEPS * NQ);

    float p0 = 0.f, p1 = 0.f, p2 = 0.f, p3 = 0.f, p4 = 0.f, p5 = 0.f;

    // Prefetch step 0 input (rows are 64B; we need the first 24B -> float4+float2).
    float4 va = __ldg(xp + 0);
    float4 vb = __ldg(xp + 1);

    #pragma unroll 2
    for (int t = 0; t < T_STEPS; t++) {
        float x0 = va.x, x1 = va.y, x2 = va.z, x3 = va.w;
        float x4 = vb.x, x5 = vb.y;

        // Prefetch next step's input early — independent of the recurrence chain.
        if (t + 1 < T_STEPS) {
            va = __ldg(xp + (t + 1) * 4);
            vb = __ldg(xp + (t + 1) * 4 + 1);
        }

        float s0, c0, s1, c1, s2, c2, s3, c3, s4, c4, s5, c5;
        __sincosf(p0 + x0, &s0, &c0);
        __sincosf(p1 + x1, &s1, &c1);
        __sincosf(p2 + x2, &s2, &c2);
        __sincosf(p3 + x3, &s3, &c3);
        __sincosf(p4 + x4, &s4, &c4);
        __sincosf(p5 + x5, &s5, &c5);

        // Prefix products of cosines (shallow tree).
        float P1 = c0 * c1;
        float P2 = P1 * c2;
        float c34 = c3 * c4;
        float P3 = P2 * c3;
        float P4 = P2 * c34;
        float P5 = P4 * c5;

        p0 = fmaf(cw0, c0, -sw0 * (s0 * s1));
        p1 = fmaf(cw1, P1, -sw1 * (s1 * s2));
        p2 = fmaf(cw2, P2, -sw2 * (s2 * s3));
        p3 = fmaf(cw3, P3, -sw3 * (s3 * s4));
        p4 = fmaf(cw4, P4, -sw4 * (s4 * s5));
        p5 = fmaf(cw5, P5, -sw5 * s5);

        // Store 24B (8-byte aligned: base is 16B-aligned, t*24 is 8-aligned).
        float2* o2 = reinterpret_cast<float2*>(op + t * NQ);
        o2[0] = make_float2(p0, p1);
        o2[1] = make_float2(p2, p3);
        o2[2] = make_float2(p4, p5);
    }
}

extern "C" void kernel_launch(void* const* d_in, const int* in_sizes, int n_in,
                              void* d_out, int out_size) {
    // Inputs per metadata order: x (B*1024*16 f32), weight (6 f32).
    const float* x = (const float*)d_in[0];
    const float* w = (const float*)d_in[1];
    // Defensive: if the order is swapped, identify by size.
    if (n_in >= 2 && in_sizes[0] == NQ) {
        const float* tmp = x; x = w; w = tmp;
    }
    float* out = (float*)d_out;

    int B = out_size / (T_STEPS * NQ);
    int blocks = (B + 31) / 32;   // 32-thread blocks -> spread warps across SMs
    qru_kernel<<<blocks, 32>>>(x, w, out, B);
}

// round 5
// speedup vs baseline: 1.6164x; 1.6164x over previous
#include <cuda_runtime.h>

// QuantumRecurrentUnit — closed-form reduction + deep software prefetch.
//
// Per step, per batch element:
//   theta_q = prev_q + x[b][t][q]          (q = 0..5)
//   P_m     = prod_{q<=m} cos(theta_q)
//   out_m   = cos(w_m)*P_m - sin(w_m)*sin(theta_m)*sin(theta_{m+1})   (m < 5)
//   out_5   = cos(w_5)*P_5 - sin(w_5)*sin(theta_5)
//   prev    = out
//
// R4 change: the recurrence chain is only ~130 cycles/step but DRAM latency
// @NAT is ~600-1000 cycles; distance-1 prefetch left ~600 cycles exposed per
// step (observed 730 cyc/step). Register ring buffer with prefetch distance
// 8 steps covers the latency. Outputs paired (2 steps = 48B) into 3 STG.128.

#define NQ 6
#define T_STEPS 1024
#define C_IN 16
#define PF 8   // prefetch distance in steps (ring depth); must divide T_STEPS

__global__ void __launch_bounds__(32, 1)
qru_kernel(const float* __restrict__ x, const float* __restrict__ w,
           float* __restrict__ out, int B) {
    int b = blockIdx.x * 32 + threadIdx.x;
    if (b >= B) return;

    // Per-wire weight sincos (runtime input, computed once).
    float cw0, sw0, cw1, sw1, cw2, sw2, cw3, sw3, cw4, sw4, cw5, sw5;
    __sincosf(__ldg(w + 0), &sw0, &cw0);
    __sincosf(__ldg(w + 1), &sw1, &cw1);
    __sincosf(__ldg(w + 2), &sw2, &cw2);
    __sincosf(__ldg(w + 3), &sw3, &cw3);
    __sincosf(__ldg(w + 4), &sw4, &cw4);
    __sincosf(__ldg(w + 5), &sw5, &cw5);

    const float*  xb  = x + (size_t)b * (T_STEPS * C_IN);
    const float4* xp4 = reinterpret_cast<const float4*>(xb);  // row t = xp4 + t*4
    const float2* xp2 = reinterpret_cast<const float2*>(xb);  // x4,x5 = xp2[t*8 + 2]
    float* __restrict__ op = out + (size_t)b * (T_STEPS * NQ);

    float p0 = 0.f, p1 = 0.f, p2 = 0.f, p3 = 0.f, p4 = 0.f, p5 = 0.f;

    // Ring buffer: PF steps of input in flight.
    float4 rA[PF];
    float2 rB[PF];
    #pragma unroll
    for (int d = 0; d < PF; d++) {
        rA[d] = __ldg(xp4 + d * 4);
        rB[d] = __ldg(xp2 + d * 8 + 2);
    }

    // Output pairing buffer (even step's 6 values).
    float q0 = 0.f, q1 = 0.f, q2 = 0.f, q3 = 0.f, q4 = 0.f, q5 = 0.f;

    for (int tb = 0; tb < T_STEPS; tb += PF) {
        bool more = (tb + PF) < T_STEPS;
        #pragma unroll
        for (int u = 0; u < PF; u++) {
            const int t = tb + u;
            float x0 = rA[u].x, x1 = rA[u].y, x2 = rA[u].z, x3 = rA[u].w;
            float x4 = rB[u].x, x5 = rB[u].y;

            // Refill this ring slot for step t+PF (issued ~PF*130 cycles
            // before its consumption — covers DRAM latency).
            if (more) {
                rA[u] = __ldg(xp4 + (t + PF) * 4);
                rB[u] = __ldg(xp2 + (t + PF) * 8 + 2);
            }

            float s0, c0, s1, c1, s2, c2, s3, c3, s4, c4, s5, c5;
            __sincosf(p0 + x0, &s0, &c0);
            __sincosf(p1 + x1, &s1, &c1);
            __sincosf(p2 + x2, &s2, &c2);
            __sincosf(p3 + x3, &s3, &c3);
            __sincosf(p4 + x4, &s4, &c4);
            __sincosf(p5 + x5, &s5, &c5);

            // Prefix products of cosines (shallow tree).
            float P1  = c0 * c1;
            float P2  = P1 * c2;
            float c34 = c3 * c4;
            float P3  = P2 * c3;
            float P4  = P2 * c34;
            float P5  = P4 * c5;

            p0 = fmaf(cw0, c0, -sw0 * (s0 * s1));
            p1 = fmaf(cw1, P1, -sw1 * (s1 * s2));
            p2 = fmaf(cw2, P2, -sw2 * (s2 * s3));
            p3 = fmaf(cw3, P3, -sw3 * (s3 * s4));
            p4 = fmaf(cw4, P4, -sw4 * (s4 * s5));
            p5 = fmaf(cw5, P5, -sw5 * s5);

            if ((u & 1) == 0) {
                // Even step: stash, store together with the odd step.
                q0 = p0; q1 = p1; q2 = p2; q3 = p3; q4 = p4; q5 = p5;
            } else {
                // Odd step: 48B of output, base offset (t-1)*24 is 16B-aligned.
                float4* o4 = reinterpret_cast<float4*>(op + (t - 1) * NQ);
                o4[0] = make_float4(q0, q1, q2, q3);
                o4[1] = make_float4(q4, q5, p0, p1);
                o4[2] = make_float4(p2, p3, p4, p5);
            }
        }
    }
}

extern "C" void kernel_launch(void* const* d_in, const int* in_sizes, int n_in,
                              void* d_out, int out_size) {
    // Inputs per metadata order: x (B*1024*16 f32), weight (6 f32).
    const float* x = (const float*)d_in[0];
    const float* w = (const float*)d_in[1];
    if (n_in >= 2 && in_sizes[0] == NQ) {  // defensive: identify by size
        const float* tmp = x; x = w; w = tmp;
    }
    float* out = (float*)d_out;

    int B = out_size / (T_STEPS * NQ);
    int blocks = (B + 31) / 32;   // 32-thread blocks -> one warp per SM/SMSP spread
    qru_kernel<<<blocks, 32>>>(x, w, out, B);
}

// round 7
// speedup vs baseline: 2.7987x; 1.7314x over previous
#include <cuda_runtime.h>

// QuantumRecurrentUnit — closed-form reduction, 2 lanes per chain.
//
// Per step: theta_q = prev_q + x_q;  P_m = prod_{q<=m} cos theta_q;
//   out_m = cos(w_m)*P_m - sin(w_m)*sin(theta_m)*sin(theta_{m+1})  (m<5)
//   out_5 = cos(w_5)*P_5 - sin(w_5)*sin(theta_5)
//
// R5/R6: per-warp MUFU throughput is the binding resource (observed
// ~460 cyc/step fits 12 MUFU x rt~32 + tail). Split each chain across a
// lane PAIR: lane0 owns wires 0-2, lane1 owns wires 3-5 -> 6 MUFU
// warp-instructions/step instead of 12, and 2x the warps (128). Coupling
// is ONE bfly shuffle: lane0 sends P2=c0c1c2, lane1 sends s3.
// (R6 resubmit: R5 never ran — GB300 container infra failure.)
//
// Uniform per-lane algebra (r = lane parity, recv = shuffled value):
//   mul = r ? recv : 1        (recv on lane1 = P2)
//   PA = mul*cA; PB = mul*(cA*cB); PC = mul*(cA*cB*cC)
//   pA = cwA*PA - swA*(sA*sB)
//   pB = cwB*PB - swB*(sB*sC)
//   pC = cwC*PC - swC*(sC * (r ? 1 : recv))   (recv on lane0 = s3)

#define NQ 6
#define T_STEPS 1024
#define C_IN 16
#define PF 8   // prefetch ring depth in steps

__global__ void __launch_bounds__(32, 1)
qru_kernel(const float* __restrict__ x, const float* __restrict__ w,
           float* __restrict__ out, int B) {
    int gt   = blockIdx.x * 32 + threadIdx.x;
    int pair = gt >> 1;          // chain index
    int r    = gt & 1;           // 0: wires 0-2, 1: wires 3-5
    if (pair >= B) return;
    // Both lanes of a pair are jointly active/inactive, so the pair-local
    // bfly shuffle under the active mask is convergence-safe.
    unsigned mask = __activemask();

    // This lane's 3 weights.
    float cwA, swA, cwB, swB, cwC, swC;
    __sincosf(__ldg(w + r * 3 + 0), &swA, &cwA);
    __sincosf(__ldg(w + r * 3 + 1), &swB, &cwB);
    __sincosf(__ldg(w + r * 3 + 2), &swC, &cwC);

    const float*  xb  = x + (size_t)pair * (T_STEPS * C_IN);
    const float4* xp4 = reinterpret_cast<const float4*>(xb);   // row t: xp4 + t*4
    const float2* xp2 = reinterpret_cast<const float2*>(xb);   // x4,x5: xp2[t*8+2]
    float* __restrict__ op = out + (size_t)pair * (T_STEPS * NQ);

    float pA = 0.f, pB = 0.f, pC = 0.f;

    // Prefetch ring: both lanes of a pair load the same addresses (broadcast,
    // no extra sectors).
    float4 rA[PF];
    float2 rB[PF];
    #pragma unroll
    for (int d = 0; d < PF; d++) {
        rA[d] = __ldg(xp4 + d * 4);
        rB[d] = __ldg(xp2 + d * 8 + 2);
    }

    const float onef = 1.0f;

    for (int tb = 0; tb < T_STEPS; tb += PF) {
        bool more = (tb + PF) < T_STEPS;
        #pragma unroll
        for (int u = 0; u < PF; u++) {
            const int t = tb + u;
            // Per-lane inputs: lane0 -> x0,x1,x2 ; lane1 -> x3,x4,x5.
            float xA = r ? rA[u].w : rA[u].x;
            float xB = r ? rB[u].x : rA[u].y;
            float xC = r ? rB[u].y : rA[u].z;

            if (more) {   // refill slot for step t+PF (covers DRAM latency)
                rA[u] = __ldg(xp4 + (t + PF) * 4);
                rB[u] = __ldg(xp2 + (t + PF) * 8 + 2);
            }

            float sA, cA, sB, cB, sC, cC;
            __sincosf(pA + xA, &sA, &cA);
            __sincosf(pB + xB, &sB, &cB);
            __sincosf(pC + xC, &sC, &cC);

            float t1  = cA * cB;
            float t2  = t1 * cC;            // lane0: P2 = c0c1c2
            float send = r ? sA : t2;       // lane1 sends s3, lane0 sends P2
            float recv = __shfl_xor_sync(mask, send, 1);

            float mul = r ? recv : onef;    // lane1: P2 from lane0
            float PA  = mul * cA;
            float PB  = mul * t1;
            float PC  = mul * t2;

            float sAB = sA * sB;
            float sBC = sB * sC;
            float sCl = sC * (r ? onef : recv);   // lane0: s2*s3, lane1: s5

            pA = fmaf(cwA, PA, -swA * sAB);
            pB = fmaf(cwB, PB, -swB * sBC);
            pC = fmaf(cwC, PC, -swC * sCl);

            // Store 12B per lane, contiguous across the pair (24B per chain).
            // lane0: {pA,pB} @ elem 0, pC @ elem 2  (byte 24t    : 8-aligned)
            // lane1: {pB,pC} @ elem 4, pA @ elem 3  (byte 24t+16 : 8-aligned)
            float* o = op + t * NQ;
            float2 v2 = r ? make_float2(pB, pC) : make_float2(pA, pB);
            *reinterpret_cast<float2*>(o + (r ? 4 : 0)) = v2;
            o[r ? 3 : 2] = r ? pA : pC;
        }
    }
}

extern "C" void kernel_launch(void* const* d_in, const int* in_sizes, int n_in,
                              void* d_out, int out_size) {
    // Inputs per metadata order: x (B*1024*16 f32), weight (6 f32).
    const float* x = (const float*)d_in[0];
    const float* w = (const float*)d_in[1];
    if (n_in >= 2 && in_sizes[0] == NQ) {  // defensive: identify by size
        const float* tmp = x; x = w; w = tmp;
    }
    float* out = (float*)d_out;

    int B = out_size / (T_STEPS * NQ);
    int threads = 2 * B;                       // 2 lanes per chain
    int blocks  = (threads + 31) / 32;         // 1 warp per block -> spread over SMs
    qru_kernel<<<blocks, 32>>>(x, w, out, B);
}

// round 12
// speedup vs baseline: 3.4217x; 1.2226x over previous
#include <cuda_runtime.h>

// QuantumRecurrentUnit — closed-form reduction, 2 lanes per chain,
// polynomial (FMA-pipe) sincos instead of MUFU.
//
// Per step: theta_q = prev_q + x_q;  P_m = prod_{q<=m} cos theta_q;
//   out_m = cos(w_m)*P_m - sin(w_m)*sin(theta_m)*sin(theta_{m+1})  (m<5)
//   out_5 = cos(w_5)*P_5 - sin(w_5)*sin(theta_5)
//
// Measured __sincosf costs ~66 warp-serial cycles each (R4->R7 slope).
// Replace with FMA/ALU sincos: k=rint(theta/pi) via 1.5*2^23 magic
// (parity bit free), Cody-Waite remainder, Taylor-9/10 on [-pi/2,pi/2],
// one sign XOR for both s and c ((-1)^k factor). ~19 instrs/sincos at rt 2.
// (Resubmit: prior two rounds were GB300 container infra failures; this
// kernel has not yet executed.)

#define NQ 6
#define T_STEPS 1024
#define C_IN 16
#define PF 16   // prefetch ring depth in steps (divides T_STEPS)

__device__ __forceinline__ void psincos(float th, float& s, float& c) {
    // k = rint(th/pi) via magic-number trick; parity bit = mantissa bit 0.
    float fk = fmaf(th, 0.3183098861837907f, 12582912.0f);
    unsigned sgn = __float_as_uint(fk) << 31;          // (-1)^k as sign bit
    float k = fk - 12582912.0f;
    // r = th - k*pi  (2-term Cody-Waite), r in [-pi/2, pi/2]
    float r = fmaf(k, -3.140625f, th);
    r = fmaf(k, -9.6765358979323846e-4f, r);
    float r2 = r * r;
    // sin(r): r + r^3*(S1 + S2 r^2 + S3 r^4 + S4 r^6 + S5 r^8)
    float ts = fmaf(-2.5052108385e-8f, r2, 2.7557319224e-6f);
    ts = fmaf(ts, r2, -1.9841269841e-4f);
    ts = fmaf(ts, r2, 8.3333333333e-3f);
    ts = fmaf(ts, r2, -1.6666666667e-1f);
    float sv = fmaf(ts * r2, r, r);
    // cos(r): 1 + r^2*(C1 + C2 r^2 + C3 r^4 + C4 r^6 + C5 r^8)
    float tc = fmaf(-2.7557319224e-7f, r2, 2.4801587302e-5f);
    tc = fmaf(tc, r2, -1.3888888889e-3f);
    tc = fmaf(tc, r2, 4.1666666667e-2f);
    tc = fmaf(tc, r2, -0.5f);
    float cv = fmaf(tc, r2, 1.0f);
    // sin(r + k*pi) = (-1)^k sin r ; cos likewise.
    s = __uint_as_float(__float_as_uint(sv) ^ sgn);
    c = __uint_as_float(__float_as_uint(cv) ^ sgn);
}

__global__ void __launch_bounds__(32, 1)
qru_kernel(const float* __restrict__ x, const float* __restrict__ w,
           float* __restrict__ out, int B) {
    int gt   = blockIdx.x * 32 + threadIdx.x;
    int pair = gt >> 1;          // chain index
    int r    = gt & 1;           // 0: wires 0-2, 1: wires 3-5
    if (pair >= B) return;
    // Both lanes of a pair are jointly active/inactive -> pair-local bfly
    // under the active mask is convergence-safe.
    unsigned mask = __activemask();

    // This lane's 3 weights (once; accuracy path).
    float cwA, swA, cwB, swB, cwC, swC;
    psincos(__ldg(w + r * 3 + 0), swA, cwA);
    psincos(__ldg(w + r * 3 + 1), swB, cwB);
    psincos(__ldg(w + r * 3 + 2), swC, cwC);

    const float*  xb  = x + (size_t)pair * (T_STEPS * C_IN);
    const float4* xp4 = reinterpret_cast<const float4*>(xb);   // row t: xp4 + t*4
    const float2* xp2 = reinterpret_cast<const float2*>(xb);   // x4,x5: xp2[t*8+2]
    float* __restrict__ op = out + (size_t)pair * (T_STEPS * NQ);

    float pA = 0.f, pB = 0.f, pC = 0.f;

    // Prefetch ring: both lanes of a pair load the same addresses (broadcast).
    float4 rA[PF];
    float2 rB[PF];
    #pragma unroll
    for (int d = 0; d < PF; d++) {
        rA[d] = __ldg(xp4 + d * 4);
        rB[d] = __ldg(xp2 + d * 8 + 2);
    }

    const float onef = 1.0f;

    for (int tb = 0; tb < T_STEPS; tb += PF) {
        bool more = (tb + PF) < T_STEPS;
        #pragma unroll
        for (int u = 0; u < PF; u++) {
            const int t = tb + u;
            // Per-lane inputs: lane0 -> x0,x1,x2 ; lane1 -> x3,x4,x5.
            float xA = r ? rA[u].w : rA[u].x;
            float xB = r ? rB[u].x : rA[u].y;
            float xC = r ? rB[u].y : rA[u].z;

            if (more) {   // refill slot for step t+PF (covers DRAM latency)
                rA[u] = __ldg(xp4 + (t + PF) * 4);
                rB[u] = __ldg(xp2 + (t + PF) * 8 + 2);
            }

            float sA, cA, sB, cB, sC, cC;
            psincos(pA + xA, sA, cA);
            psincos(pB + xB, sB, cB);
            psincos(pC + xC, sC, cC);

            float t1  = cA * cB;
            float t2  = t1 * cC;            // lane0: P2 = c0c1c2
            float send = r ? sA : t2;       // lane1 sends s3, lane0 sends P2
            float recv = __shfl_xor_sync(mask, send, 1);

            float mul = r ? recv : onef;    // lane1: P2 from lane0
            float PA  = mul * cA;
            float PB  = mul * t1;
            float PC  = mul * t2;

            float sAB = sA * sB;
            float sBC = sB * sC;
            float sCl = sC * (r ? onef : recv);   // lane0: s2*s3, lane1: s5

            pA = fmaf(cwA, PA, -swA * sAB);
            pB = fmaf(cwB, PB, -swB * sBC);
            pC = fmaf(cwC, PC, -swC * sCl);

            // Store 12B per lane, contiguous across the pair (24B per chain).
            // lane0: {pA,pB} @ elem 0, pC @ elem 2  (byte 24t    : 8-aligned)
            // lane1: {pB,pC} @ elem 4, pA @ elem 3  (byte 24t+16 : 8-aligned)
            float* o = op + t * NQ;
            float2 v2 = r ? make_float2(pB, pC) : make_float2(pA, pB);
            *reinterpret_cast<float2*>(o + (r ? 4 : 0)) = v2;
            o[r ? 3 : 2] = r ? pA : pC;
        }
    }
}

extern "C" void kernel_launch(void* const* d_in, const int* in_sizes, int n_in,
                              void* d_out, int out_size) {
    // Inputs per metadata order: x (B*1024*16 f32), weight (6 f32).
    const float* x = (const float*)d_in[0];
    const float* w = (const float*)d_in[1];
    if (n_in >= 2 && in_sizes[0] == NQ) {  // defensive: identify by size
        const float* tmp = x; x = w; w = tmp;
    }
    float* out = (float*)d_out;

    int B = out_size / (T_STEPS * NQ);
    int threads = 2 * B;                       // 2 lanes per chain
    int blocks  = (threads + 31) / 32;         // 1 warp per block -> spread over SMs
    qru_kernel<<<blocks, 32>>>(x, w, out, B);
}